// round 10
// baseline (speedup 1.0000x reference)
#include <cuda_runtime.h>
#include <math.h>

#define BB     4
#define TT     2048
#define NTOK   (BB*TT)          // 8192
#define DM     128
#define NH     4
#define DH     32
#define WIN    64
#define DFFN   256
#define DQKV   384
#define TILE   16               // tokens per block in fused GEMM kernels
#define NBLK   (NTOK/TILE)      // 512

typedef unsigned long long u64;

// Scratch (no cudaMalloc allowed)
__device__ float g_h[NTOK*DM];       // 4 MB
__device__ float g_qkv[NTOK*DQKV];   // 12 MB
__device__ float g_att[NTOK*DM];     // 4 MB

// ---------------------------------------------------------------------------
// f32x2 packed helpers (FFMA2 — ptxas never auto-fuses; PTX-only path)
// ---------------------------------------------------------------------------
__device__ __forceinline__ u64 pack2(float lo, float hi) {
    u64 r;
    asm("mov.b64 %0, {%1, %2};" : "=l"(r) : "f"(lo), "f"(hi));
    return r;
}
__device__ __forceinline__ void fma2(u64& acc, u64 x, u64 w) {
    asm("fma.rn.f32x2 %0, %1, %2, %3;" : "=l"(acc) : "l"(x), "l"(w), "l"(acc));
}
__device__ __forceinline__ float unpack_sum(u64 a) {
    float lo, hi;
    asm("mov.b64 {%0, %1}, %2;" : "=f"(lo), "=f"(hi) : "l"(a));
    return lo + hi;
}

// ---------------------------------------------------------------------------
// 8-token GEMM column via f32x2: out[m] = bias + sum_k X[m][k] * W[k][c]
// X rows are LD floats (16B-aligned at k0 multiples of 4, broadcast LDS.128).
// Even/odd k accumulate in the two f32x2 halves; summed at the end.
// ---------------------------------------------------------------------------
template<int K, int LD>
__device__ __forceinline__ void gemm8(const float* Xb, const float* __restrict__ W,
                                      int wstride, int c, float bias, float* o)
{
    u64 acc[8];
    u64 binit = pack2(bias, 0.0f);
    #pragma unroll
    for (int m = 0; m < 8; m++) acc[m] = binit;
    #pragma unroll 4
    for (int k0 = 0; k0 < K; k0 += 4) {
        const float* wp = W + (size_t)k0*wstride + c;
        float w0 = wp[0];
        float w1 = wp[wstride];
        float w2 = wp[2*wstride];
        float w3 = wp[3*wstride];
        u64 w01 = pack2(w0, w1), w23 = pack2(w2, w3);
        #pragma unroll
        for (int m = 0; m < 8; m++) {
            ulonglong2 xv = *reinterpret_cast<const ulonglong2*>(Xb + (size_t)m*LD + k0);
            fma2(acc[m], xv.x, w01);
            fma2(acc[m], xv.y, w23);
        }
    }
    #pragma unroll
    for (int m = 0; m < 8; m++) o[m] = unpack_sum(acc[m]);
}

// ===========================================================================
// Kernel 1: in_proj (concat->Lin16x128->ReLU->Lin128x128 + PE) + QKV layer 0
// ===========================================================================
__global__ void __launch_bounds__(256, 4)
k_pre(const float* __restrict__ E,  const float* __restrict__ rho,
      const float* __restrict__ W1, const float* __restrict__ b1,
      const float* __restrict__ W2, const float* __restrict__ b2,
      const float* __restrict__ Wq, const float* __restrict__ bq)
{
    __shared__ float xs[TILE][16];
    __shared__ float sHid[TILE][DM];
    __shared__ float sH[TILE][DM];
    int t = threadIdx.x;
    int m0 = blockIdx.x * TILE;

    // load concat(E, rho): 256 elements, one per thread
    {
        int m = t >> 4, k = t & 15;
        int r = m0 + m;
        xs[m][k] = (k < 8) ? E[r*8 + k] : rho[r*8 + (k-8)];
    }
    __syncthreads();

    int g = t >> 7, c = t & 127;
    int mb = g * 8;
    float f[8];

    // hidden = relu(x @ W1 + b1)
    gemm8<16,16>(&xs[mb][0], W1, DM, c, b1[c], f);
    #pragma unroll
    for (int m = 0; m < 8; m++) sHid[mb+m][c] = fmaxf(f[m], 0.0f);
    __syncthreads();

    // h = hidden @ W2 + b2 + PE
    gemm8<DM,DM>(&sHid[mb][0], W2, DM, c, b2[c], f);
    {
        int i = c >> 1;
        float invf = expf(-9.210340371976184f * (float)i / 64.0f);
        #pragma unroll
        for (int m = 0; m < 8; m++) {
            int r = m0 + mb + m;
            int pos = r & (TT - 1);
            float ang = (float)pos * invf;
            float pe = (c & 1) ? cosf(ang) : sinf(ang);
            float h = f[m] + pe;
            sH[mb+m][c] = h;
            g_h[r*DM + c] = h;
        }
    }
    __syncthreads();

    // QKV for layer 0
    #pragma unroll
    for (int pass = 0; pass < 3; pass++) {
        int off = pass * DM;
        gemm8<DM,DM>(&sH[mb][0], Wq, DQKV, off + c, bq[off + c], f);
        #pragma unroll
        for (int m = 0; m < 8; m++)
            g_qkv[(size_t)(m0+mb+m)*DQKV + off + c] = f[m];
    }
}

// ===========================================================================
// Kernel 2: tiled banded attention.
// Block = (qtile of 32, head, batch). 256 threads (8 warps, 4 queries/warp).
// K row-major pad-36 (conflict-free float4), V row-major, Q in regs, ps float4.
// ===========================================================================
__global__ void __launch_bounds__(256, 4)
k_attn()
{
    int qt = blockIdx.x, h = blockIdx.y, b = blockIdx.z;
    int t = threadIdx.x, w = t >> 5, l = t & 31;
    int qstart = qt * 32;
    int r0 = (qstart >= WIN-1) ? (qstart - (WIN-1)) : 0;
    int nrows = qstart + 32 - r0;           // <= 95

    __shared__ float Ks[95][36];   // pad 36: 8-lane LDS.128 wavefronts conflict-free
    __shared__ float Vs[95][DH];
    __shared__ float qs[32][DH];
    __shared__ float ps[8][WIN];

    const float* baseQ = g_qkv + (size_t)(b*TT + qstart)*DQKV + h*DH;
    for (int idx = t; idx < 32*DH; idx += 256) {
        int qi = idx >> 5, d = idx & 31;
        qs[qi][d] = baseQ[qi*DQKV + d];
    }
    // stage K/V over full 95 rows; zero-fill beyond window (NaN-safe for masked math)
    const float* baseK = g_qkv + (size_t)(b*TT + r0)*DQKV + DM + h*DH;
    const float* baseV = baseK + DM;
    for (int idx = t; idx < 95*DH; idx += 256) {
        int r = idx >> 5, d = idx & 31;
        float kv = 0.0f, vv = 0.0f;
        if (r < nrows) { kv = baseK[(size_t)r*DQKV + d]; vv = baseV[(size_t)r*DQKV + d]; }
        Ks[r][d] = kv;
        Vs[r][d] = vv;
    }
    __syncthreads();

    const float scale = 0.17677669529663687f;   // 1/sqrt(32)

    #pragma unroll
    for (int s = 0; s < 4; s++) {
        int qi = w*4 + s;
        int iglob = qstart + qi;
        int jlo = (iglob >= WIN-1) ? (iglob - (WIN-1)) : 0;
        int ni = iglob - jlo + 1;           // 1..64
        int base = jlo - r0;                // >= 0; base+63 <= 94

        // scores: lane computes j = l and j = l+32 via float4 dot products
        const float4* qp  = (const float4*)qs[qi];
        const float4* k0p = (const float4*)Ks[base + l];
        const float4* k1p = (const float4*)Ks[base + l + 32];
        float a0a = 0.f, a0b = 0.f, a1a = 0.f, a1b = 0.f;
        #pragma unroll
        for (int dd = 0; dd < 8; dd += 2) {
            float4 q0 = qp[dd], q1 = qp[dd+1];
            float4 ka = k0p[dd], kb = k0p[dd+1];
            a0a = fmaf(q0.x, ka.x, fmaf(q0.y, ka.y, fmaf(q0.z, ka.z, fmaf(q0.w, ka.w, a0a))));
            a0b = fmaf(q1.x, kb.x, fmaf(q1.y, kb.y, fmaf(q1.z, kb.z, fmaf(q1.w, kb.w, a0b))));
            float4 kc = k1p[dd], kd = k1p[dd+1];
            a1a = fmaf(q0.x, kc.x, fmaf(q0.y, kc.y, fmaf(q0.z, kc.z, fmaf(q0.w, kc.w, a1a))));
            a1b = fmaf(q1.x, kd.x, fmaf(q1.y, kd.y, fmaf(q1.z, kd.z, fmaf(q1.w, kd.w, a1b))));
        }
        float a0 = a0a + a0b;
        float a1 = a1a + a1b;
        a0 = (l      < ni) ? a0*scale : -1e30f;
        a1 = (l + 32 < ni) ? a1*scale : -1e30f;

        float mx = fmaxf(a0, a1);
        #pragma unroll
        for (int off = 16; off > 0; off >>= 1)
            mx = fmaxf(mx, __shfl_xor_sync(0xffffffffu, mx, off));

        float p0 = (l      < ni) ? __expf(a0 - mx) : 0.0f;
        float p1 = (l + 32 < ni) ? __expf(a1 - mx) : 0.0f;
        ps[w][l]      = p0;
        ps[w][l + 32] = p1;
        float sum = p0 + p1;
        #pragma unroll
        for (int off = 16; off > 0; off >>= 1)
            sum += __shfl_xor_sync(0xffffffffu, sum, off);
        float rs = 1.0f / sum;
        __syncwarp();

        // AV: lane = head dim; ps as float4 broadcasts; 4 accumulator chains.
        // Full 64-j loop is safe: ps zeros beyond ni, Vs zeros beyond window.
        float acc0 = 0.f, acc1 = 0.f, acc2 = 0.f, acc3 = 0.f;
        const float4* pp = (const float4*)ps[w];
        #pragma unroll
        for (int j4 = 0; j4 < 16; j4++) {
            float4 pv = pp[j4];
            int jb = base + j4*4;
            acc0 = fmaf(pv.x, Vs[jb+0][l], acc0);
            acc1 = fmaf(pv.y, Vs[jb+1][l], acc1);
            acc2 = fmaf(pv.z, Vs[jb+2][l], acc2);
            acc3 = fmaf(pv.w, Vs[jb+3][l], acc3);
        }
        g_att[(size_t)(b*TT + iglob)*DM + h*DH + l] = ((acc0+acc1) + (acc2+acc3)) * rs;
        __syncwarp();
    }
}

// ===========================================================================
// LayerNorm over 16 tokens, 256 threads. sR -> sOut (normalized).
// ===========================================================================
__device__ __forceinline__ void ln_16(float (&sR)[TILE][DM], float (&sOut)[TILE][DM],
                                      float* muS, float* rsS,
                                      const float* __restrict__ gw,
                                      const float* __restrict__ bw, int t)
{
    int w = t >> 5, l = t & 31;
    #pragma unroll
    for (int s = 0; s < 2; s++) {
        int mm = w*2 + s;
        float v = sR[mm][l] + sR[mm][l+32] + sR[mm][l+64] + sR[mm][l+96];
        #pragma unroll
        for (int off = 16; off > 0; off >>= 1)
            v += __shfl_xor_sync(0xffffffffu, v, off);
        float mean = v * (1.0f/128.0f);
        float d0 = sR[mm][l   ] - mean;
        float d1 = sR[mm][l+32] - mean;
        float d2 = sR[mm][l+64] - mean;
        float d3 = sR[mm][l+96] - mean;
        float q = d0*d0 + d1*d1 + d2*d2 + d3*d3;
        #pragma unroll
        for (int off = 16; off > 0; off >>= 1)
            q += __shfl_xor_sync(0xffffffffu, q, off);
        if (l == 0) { muS[mm] = mean; rsS[mm] = rsqrtf(q * (1.0f/128.0f) + 1e-5f); }
    }
    __syncthreads();
    int g = t >> 7, c = t & 127;
    float gg = gw[c], bb = bw[c];
    #pragma unroll
    for (int m = 0; m < 8; m++) {
        int mm = g*8 + m;
        sOut[mm][c] = (sR[mm][c] - muS[mm]) * rsS[mm] * gg + bb;
    }
    __syncthreads();
}

// ===========================================================================
// Kernel 3: fused post-attention block (f32x2 GEMMs):
//   h = LN1(h + att@Wo + bo);  h = LN2(h + relu(h@Wf1+bf1)@Wf2 + bf2)
//   then QKV for next layer (last==0) or head output (last==1)
// ===========================================================================
__global__ void __launch_bounds__(256, 4)
k_post(const float* __restrict__ Wo,  const float* __restrict__ bo,
       const float* __restrict__ g1,  const float* __restrict__ b1n,
       const float* __restrict__ Wf1, const float* __restrict__ bf1,
       const float* __restrict__ Wf2, const float* __restrict__ bf2,
       const float* __restrict__ g2,  const float* __restrict__ b2n,
       const float* __restrict__ Wq,  const float* __restrict__ bq,
       const float* __restrict__ Wh,  const float* __restrict__ bh,
       float* __restrict__ out, int last)
{
    __shared__ float sH[TILE][DM];
    __shared__ float sA[TILE][DM];
    __shared__ float sR[TILE][DM];
    __shared__ float sU[TILE][DFFN];
    __shared__ float muS[TILE], rsS[TILE];

    int t = threadIdx.x;
    int m0 = blockIdx.x * TILE;
    int g = t >> 7, c = t & 127;
    int mb = g * 8;
    float f[8];

    for (int idx = t; idx < TILE*DM; idx += 256) {
        int m = idx >> 7, cc = idx & 127;
        sH[m][cc] = g_h  [(size_t)(m0+m)*DM + cc];
        sA[m][cc] = g_att[(size_t)(m0+m)*DM + cc];
    }
    __syncthreads();

    // oproj + residual
    gemm8<DM,DM>(&sA[mb][0], Wo, DM, c, bo[c], f);
    #pragma unroll
    for (int m = 0; m < 8; m++) sR[mb+m][c] = sH[mb+m][c] + f[m];
    __syncthreads();

    ln_16(sR, sH, muS, rsS, g1, b1n, t);   // sH = LN1 output

    // FF1: two sequential channel passes (c, then c+128) to cap registers
    gemm8<DM,DM>(&sH[mb][0], Wf1, DFFN, c, bf1[c], f);
    #pragma unroll
    for (int m = 0; m < 8; m++) sU[mb+m][c] = fmaxf(f[m], 0.0f);
    gemm8<DM,DM>(&sH[mb][0], Wf1, DFFN, c + 128, bf1[c + 128], f);
    #pragma unroll
    for (int m = 0; m < 8; m++) sU[mb+m][c+128] = fmaxf(f[m], 0.0f);
    __syncthreads();

    // FF2 + residual
    gemm8<DFFN,DFFN>(&sU[mb][0], Wf2, DM, c, bf2[c], f);
    #pragma unroll
    for (int m = 0; m < 8; m++) sR[mb+m][c] = sH[mb+m][c] + f[m];
    __syncthreads();

    ln_16(sR, sH, muS, rsS, g2, b2n, t);   // sH = LN2 output = new h

    if (!last) {
        // write new h + QKV for next layer
        #pragma unroll
        for (int m = 0; m < 8; m++) g_h[(size_t)(m0+mb+m)*DM + c] = sH[mb+m][c];

        #pragma unroll
        for (int pass = 0; pass < 3; pass++) {
            int off = pass * DM;
            gemm8<DM,DM>(&sH[mb][0], Wq, DQKV, off + c, bq[off + c], f);
            #pragma unroll
            for (int m = 0; m < 8; m++)
                g_qkv[(size_t)(m0+mb+m)*DQKV + off + c] = f[m];
        }
    } else {
        // head: 16 tokens x 8 outputs = 128 values
        if (t < TILE*8) {
            int m = t >> 3, cc = t & 7;
            float acc = bh[cc];
            #pragma unroll 8
            for (int k = 0; k < DM; k++)
                acc = fmaf(sH[m][k], Wh[k*8 + cc], acc);
            out[(m0+m)*8 + cc] = acc;
        }
    }
}

// ===========================================================================
extern "C" void kernel_launch(void* const* d_in, const int* in_sizes, int n_in,
                              void* d_out, int out_size)
{
    const float* E      = (const float*)d_in[0];
    const float* rho    = (const float*)d_in[1];
    const float* W_in1  = (const float*)d_in[2];
    const float* b_in1  = (const float*)d_in[3];
    const float* W_in2  = (const float*)d_in[4];
    const float* b_in2  = (const float*)d_in[5];
    const float* Wqkv   = (const float*)d_in[6];
    const float* bqkv   = (const float*)d_in[7];
    const float* Wo     = (const float*)d_in[8];
    const float* bo     = (const float*)d_in[9];
    const float* ln1g   = (const float*)d_in[10];
    const float* ln1b   = (const float*)d_in[11];
    const float* Wff1   = (const float*)d_in[12];
    const float* bff1   = (const float*)d_in[13];
    const float* Wff2   = (const float*)d_in[14];
    const float* bff2   = (const float*)d_in[15];
    const float* ln2g   = (const float*)d_in[16];
    const float* ln2b   = (const float*)d_in[17];
    const float* W_head = (const float*)d_in[18];
    const float* b_head = (const float*)d_in[19];
    float* out = (float*)d_out;

    k_pre<<<NBLK, 256>>>(E, rho, W_in1, b_in1, W_in2, b_in2, Wqkv, bqkv);

    dim3 agrid(TT/32, NH, BB);
    for (int l = 0; l < 3; l++) {
        k_attn<<<agrid, 256>>>();
        int last = (l == 2);
        k_post<<<NBLK, 256>>>(Wo + (size_t)l*DM*DM, bo + l*DM,
                              ln1g + l*DM, ln1b + l*DM,
                              Wff1 + (size_t)l*DM*DFFN, bff1 + l*DFFN,
                              Wff2 + (size_t)l*DFFN*DM, bff2 + l*DM,
                              ln2g + l*DM, ln2b + l*DM,
                              Wqkv + (size_t)(l+1)*DM*DQKV, bqkv + (l+1)*DQKV,
                              W_head, b_head, out, last);
    }
}

// round 13
// speedup vs baseline: 1.1747x; 1.1747x over previous
#include <cuda_runtime.h>
#include <math.h>

#define BB     4
#define TT     2048
#define NTOK   (BB*TT)          // 8192
#define DM     128
#define NH     4
#define DH     32
#define WIN    64
#define DFFN   256
#define DQKV   384
#define TILE   16               // tokens per block in k_pre
#define NBLK   (NTOK/TILE)      // 512
#define TILE2  32               // tokens per block in k_post
#define NBLK2  (NTOK/TILE2)     // 256

// k_post dynamic shared: A[32*128] + B[32*128] + C[32*256] + mu[32] + rs[32]
#define SMEM_POST ((4096 + 4096 + 8192 + 64) * 4)

// Scratch (no cudaMalloc allowed)
__device__ float g_h[NTOK*DM];       // 4 MB
__device__ float g_qkv[NTOK*DQKV];   // 12 MB
__device__ float g_att[NTOK*DM];     // 4 MB

// ===========================================================================
// Kernel 1: in_proj (concat->Lin16x128->ReLU->Lin128x128 + PE) + QKV layer 0
// (byte-identical to the measured 374.9us version)
// ===========================================================================
__global__ void __launch_bounds__(256, 4)
k_pre(const float* __restrict__ E,  const float* __restrict__ rho,
      const float* __restrict__ W1, const float* __restrict__ b1,
      const float* __restrict__ W2, const float* __restrict__ b2,
      const float* __restrict__ Wq, const float* __restrict__ bq)
{
    __shared__ float xs[TILE][16];
    __shared__ float sHid[TILE][DM];
    __shared__ float sH[TILE][DM];
    int t = threadIdx.x;
    int m0 = blockIdx.x * TILE;

    {
        int m = t >> 4, k = t & 15;
        int r = m0 + m;
        xs[m][k] = (k < 8) ? E[r*8 + k] : rho[r*8 + (k-8)];
    }
    __syncthreads();

    int g = t >> 7, c = t & 127;
    int mb = g * 8;

    // hidden = relu(x @ W1 + b1)
    {
        float acc[8];
        float bv = b1[c];
        #pragma unroll
        for (int m = 0; m < 8; m++) acc[m] = bv;
        #pragma unroll
        for (int k0 = 0; k0 < 16; k0 += 4) {
            float w0 = W1[(k0+0)*DM + c];
            float w1 = W1[(k0+1)*DM + c];
            float w2 = W1[(k0+2)*DM + c];
            float w3 = W1[(k0+3)*DM + c];
            #pragma unroll
            for (int m = 0; m < 8; m++) {
                float4 x = *(const float4*)&xs[mb+m][k0];
                acc[m] = fmaf(x.x, w0, fmaf(x.y, w1, fmaf(x.z, w2, fmaf(x.w, w3, acc[m]))));
            }
        }
        #pragma unroll
        for (int m = 0; m < 8; m++) sHid[mb+m][c] = fmaxf(acc[m], 0.0f);
    }
    __syncthreads();

    // h = hidden @ W2 + b2 + PE
    {
        float acc[8];
        float bv = b2[c];
        #pragma unroll
        for (int m = 0; m < 8; m++) acc[m] = bv;
        #pragma unroll 4
        for (int k0 = 0; k0 < DM; k0 += 4) {
            float w0 = W2[(k0+0)*DM + c];
            float w1 = W2[(k0+1)*DM + c];
            float w2 = W2[(k0+2)*DM + c];
            float w3 = W2[(k0+3)*DM + c];
            #pragma unroll
            for (int m = 0; m < 8; m++) {
                float4 x = *(const float4*)&sHid[mb+m][k0];
                acc[m] = fmaf(x.x, w0, fmaf(x.y, w1, fmaf(x.z, w2, fmaf(x.w, w3, acc[m]))));
            }
        }
        int i = c >> 1;
        float invf = expf(-9.210340371976184f * (float)i / 64.0f);
        #pragma unroll
        for (int m = 0; m < 8; m++) {
            int r = m0 + mb + m;
            int pos = r & (TT - 1);
            float ang = (float)pos * invf;
            float pe = (c & 1) ? cosf(ang) : sinf(ang);
            float h = acc[m] + pe;
            sH[mb+m][c] = h;
            g_h[r*DM + c] = h;
        }
    }
    __syncthreads();

    // QKV for layer 0
    #pragma unroll
    for (int pass = 0; pass < 3; pass++) {
        int off = pass * DM;
        float acc[8];
        float bv = bq[off + c];
        #pragma unroll
        for (int m = 0; m < 8; m++) acc[m] = bv;
        #pragma unroll 4
        for (int k0 = 0; k0 < DM; k0 += 4) {
            float w0 = Wq[(k0+0)*DQKV + off + c];
            float w1 = Wq[(k0+1)*DQKV + off + c];
            float w2 = Wq[(k0+2)*DQKV + off + c];
            float w3 = Wq[(k0+3)*DQKV + off + c];
            #pragma unroll
            for (int m = 0; m < 8; m++) {
                float4 x = *(const float4*)&sH[mb+m][k0];
                acc[m] = fmaf(x.x, w0, fmaf(x.y, w1, fmaf(x.z, w2, fmaf(x.w, w3, acc[m]))));
            }
        }
        #pragma unroll
        for (int m = 0; m < 8; m++)
            g_qkv[(size_t)(m0+mb+m)*DQKV + off + c] = acc[m];
    }
}

// ===========================================================================
// Kernel 2: tiled banded attention — byte-identical to measured 374.9us version.
// ===========================================================================
__global__ void __launch_bounds__(256, 4)
k_attn()
{
    int qt = blockIdx.x, h = blockIdx.y, b = blockIdx.z;
    int t = threadIdx.x, w = t >> 5, l = t & 31;
    int qstart = qt * 32;
    int r0 = (qstart >= WIN-1) ? (qstart - (WIN-1)) : 0;
    int nrows = qstart + 32 - r0;           // <= 95

    __shared__ float KT[DH][97];
    __shared__ float Vs[95][DH];
    __shared__ float qs[32][DH];
    __shared__ float ps[8][WIN];

    const float* baseQ = g_qkv + (size_t)(b*TT + qstart)*DQKV + h*DH;
    for (int idx = t; idx < 32*DH; idx += 256) {
        int qi = idx >> 5, d = idx & 31;
        qs[qi][d] = baseQ[qi*DQKV + d];
    }
    const float* baseK = g_qkv + (size_t)(b*TT + r0)*DQKV + DM + h*DH;
    const float* baseV = baseK + DM;
    for (int idx = t; idx < nrows*DH; idx += 256) {
        int r = idx >> 5, d = idx & 31;
        KT[d][r] = baseK[r*DQKV + d];
        Vs[r][d] = baseV[r*DQKV + d];
    }
    __syncthreads();

    const float scale = 0.17677669529663687f;   // 1/sqrt(32)

    #pragma unroll
    for (int s = 0; s < 4; s++) {
        int qi = w*4 + s;
        int iglob = qstart + qi;
        int jlo = (iglob >= WIN-1) ? (iglob - (WIN-1)) : 0;
        int ni = iglob - jlo + 1;           // 1..64
        int base = jlo - r0;                // >= 0, base+63 <= nrows-1

        float a0 = 0.f, a1 = 0.f;
        #pragma unroll
        for (int d = 0; d < DH; d++) {
            float q = qs[qi][d];
            a0 = fmaf(q, KT[d][base + l],      a0);
            a1 = fmaf(q, KT[d][base + l + 32], a1);
        }
        a0 = (l      < ni) ? a0*scale : -1e30f;
        a1 = (l + 32 < ni) ? a1*scale : -1e30f;

        float mx = fmaxf(a0, a1);
        #pragma unroll
        for (int off = 16; off > 0; off >>= 1)
            mx = fmaxf(mx, __shfl_xor_sync(0xffffffffu, mx, off));

        float p0 = (l      < ni) ? __expf(a0 - mx) : 0.0f;
        float p1 = (l + 32 < ni) ? __expf(a1 - mx) : 0.0f;
        ps[w][l]      = p0;
        ps[w][l + 32] = p1;
        float sum = p0 + p1;
        #pragma unroll
        for (int off = 16; off > 0; off >>= 1)
            sum += __shfl_xor_sync(0xffffffffu, sum, off);
        __syncwarp();

        float acc0 = 0.f, acc1 = 0.f, acc2 = 0.f, acc3 = 0.f;
        int j = 0;
        for (; j + 3 < ni; j += 4) {
            acc0 = fmaf(ps[w][j],   Vs[base+j][l],   acc0);
            acc1 = fmaf(ps[w][j+1], Vs[base+j+1][l], acc1);
            acc2 = fmaf(ps[w][j+2], Vs[base+j+2][l], acc2);
            acc3 = fmaf(ps[w][j+3], Vs[base+j+3][l], acc3);
        }
        for (; j < ni; j++)
            acc0 = fmaf(ps[w][j], Vs[base+j][l], acc0);

        float rs = 1.0f / sum;
        g_att[(size_t)(b*TT + iglob)*DM + h*DH + l] = ((acc0+acc1) + (acc2+acc3)) * rs;
        __syncwarp();
    }
}

// ---------------------------------------------------------------------------
// 8-token x 2-column scalar GEMM: o{0,1}[m] = b{0,1} + sum_k X[m][k]*W[k][c{0,1}]
// X rows LD floats, 16B-aligned; each LDS.128 of X feeds 8 FMAs (2 cols).
// ---------------------------------------------------------------------------
template<int K, int LD>
__device__ __forceinline__ void gemm8x2(const float* Xb, const float* __restrict__ W,
                                        int wstride, int c0, int c1,
                                        float b0, float b1, float* o0, float* o1)
{
    float a0[8], a1[8];
    #pragma unroll
    for (int m = 0; m < 8; m++) { a0[m] = b0; a1[m] = b1; }
    #pragma unroll 4
    for (int k0 = 0; k0 < K; k0 += 4) {
        const float* wp = W + (size_t)k0*wstride;
        float w00 = wp[c0], w01 = wp[wstride + c0], w02 = wp[2*wstride + c0], w03 = wp[3*wstride + c0];
        float w10 = wp[c1], w11 = wp[wstride + c1], w12 = wp[2*wstride + c1], w13 = wp[3*wstride + c1];
        #pragma unroll
        for (int m = 0; m < 8; m++) {
            float4 x = *(const float4*)(Xb + (size_t)m*LD + k0);
            a0[m] = fmaf(x.x, w00, fmaf(x.y, w01, fmaf(x.z, w02, fmaf(x.w, w03, a0[m]))));
            a1[m] = fmaf(x.x, w10, fmaf(x.y, w11, fmaf(x.z, w12, fmaf(x.w, w13, a1[m]))));
        }
    }
    #pragma unroll
    for (int m = 0; m < 8; m++) { o0[m] = a0[m]; o1[m] = a1[m]; }
}

// ---------------------------------------------------------------------------
// LayerNorm over 32 tokens (B -> A), 256 threads (8 warps x 4 tokens).
// ---------------------------------------------------------------------------
__device__ __forceinline__ void ln32(const float* B, float* A, float* muS, float* rsS,
                                     const float* __restrict__ gw,
                                     const float* __restrict__ bw, int t)
{
    int w = t >> 5, l = t & 31;
    #pragma unroll
    for (int s = 0; s < 4; s++) {
        int mm = w*4 + s;
        const float* r = B + mm*DM;
        float v = r[l] + r[l+32] + r[l+64] + r[l+96];
        #pragma unroll
        for (int off = 16; off > 0; off >>= 1)
            v += __shfl_xor_sync(0xffffffffu, v, off);
        float mean = v * (1.0f/128.0f);
        float d0 = r[l   ] - mean;
        float d1 = r[l+32] - mean;
        float d2 = r[l+64] - mean;
        float d3 = r[l+96] - mean;
        float q = d0*d0 + d1*d1 + d2*d2 + d3*d3;
        #pragma unroll
        for (int off = 16; off > 0; off >>= 1)
            q += __shfl_xor_sync(0xffffffffu, q, off);
        if (l == 0) { muS[mm] = mean; rsS[mm] = rsqrtf(q * (1.0f/128.0f) + 1e-5f); }
    }
    __syncthreads();
    for (int idx = t; idx < TILE2*DM; idx += 256) {
        int m = idx >> 7, c = idx & 127;
        A[idx] = (B[idx] - muS[m]) * rsS[m] * gw[c] + bw[c];
    }
    __syncthreads();
}

// ===========================================================================
// Kernel 3: fused post-attention block, TILE2=32 tokens, 2 cols/thread.
// Dynamic shared: A[32][128], B[32][128], C[32][256] (att staging / FF hidden).
// ===========================================================================
__global__ void __launch_bounds__(256, 2)
k_post(const float* __restrict__ Wo,  const float* __restrict__ bo,
       const float* __restrict__ g1,  const float* __restrict__ b1n,
       const float* __restrict__ Wf1, const float* __restrict__ bf1,
       const float* __restrict__ Wf2, const float* __restrict__ bf2,
       const float* __restrict__ g2,  const float* __restrict__ b2n,
       const float* __restrict__ Wq,  const float* __restrict__ bq,
       const float* __restrict__ Wh,  const float* __restrict__ bh,
       float* __restrict__ out, int last)
{
    extern __shared__ float smem[];
    float* A   = smem;              // [32][128] residual / LN out
    float* Bv  = A + TILE2*DM;      // [32][128] pre-LN accumulator
    float* C   = Bv + TILE2*DM;     // [32][256] att staging, then FF hidden
    float* muS = C + TILE2*DFFN;
    float* rsS = muS + TILE2;

    int t = threadIdx.x;
    int m0 = blockIdx.x * TILE2;
    int g  = t >> 6;                // 4 token-groups of 8
    int cp = t & 63;                // column pair: cp, cp+64
    int mb = g * 8;
    float f0[8], f1[8];

    // stage h -> A, att -> C (as [32][128])
    for (int idx = t; idx < TILE2*DM; idx += 256) {
        A[idx] = g_h  [(size_t)m0*DM + idx];
        C[idx] = g_att[(size_t)m0*DM + idx];
    }
    __syncthreads();

    // oproj + residual: B = A + att @ Wo + bo
    gemm8x2<DM,DM>(C + mb*DM, Wo, DM, cp, cp+64, bo[cp], bo[cp+64], f0, f1);
    #pragma unroll
    for (int m = 0; m < 8; m++) {
        int row = (mb+m)*DM;
        Bv[row + cp]      = A[row + cp]      + f0[m];
        Bv[row + cp + 64] = A[row + cp + 64] + f1[m];
    }
    __syncthreads();

    ln32(Bv, A, muS, rsS, g1, b1n, t);      // A = LN1 output

    // FF1: C = relu(A @ Wf1 + bf1), 256 cols in two passes
    gemm8x2<DM,DM>(A + mb*DM, Wf1, DFFN, cp, cp+64, bf1[cp], bf1[cp+64], f0, f1);
    #pragma unroll
    for (int m = 0; m < 8; m++) {
        int row = (mb+m)*DFFN;
        C[row + cp]      = fmaxf(f0[m], 0.0f);
        C[row + cp + 64] = fmaxf(f1[m], 0.0f);
    }
    gemm8x2<DM,DM>(A + mb*DM, Wf1, DFFN, cp+128, cp+192, bf1[cp+128], bf1[cp+192], f0, f1);
    #pragma unroll
    for (int m = 0; m < 8; m++) {
        int row = (mb+m)*DFFN;
        C[row + cp + 128] = fmaxf(f0[m], 0.0f);
        C[row + cp + 192] = fmaxf(f1[m], 0.0f);
    }
    __syncthreads();

    // FF2 + residual: B = A + C @ Wf2 + bf2
    gemm8x2<DFFN,DFFN>(C + mb*DFFN, Wf2, DM, cp, cp+64, bf2[cp], bf2[cp+64], f0, f1);
    #pragma unroll
    for (int m = 0; m < 8; m++) {
        int row = (mb+m)*DM;
        Bv[row + cp]      = A[row + cp]      + f0[m];
        Bv[row + cp + 64] = A[row + cp + 64] + f1[m];
    }
    __syncthreads();

    ln32(Bv, A, muS, rsS, g2, b2n, t);      // A = LN2 output = new h

    if (!last) {
        // write new h + QKV for next layer
        for (int idx = t; idx < TILE2*DM; idx += 256)
            g_h[(size_t)m0*DM + idx] = A[idx];

        #pragma unroll
        for (int pass = 0; pass < 3; pass++) {
            int off = pass * DM;
            gemm8x2<DM,DM>(A + mb*DM, Wq, DQKV, off + cp, off + cp + 64,
                           bq[off + cp], bq[off + cp + 64], f0, f1);
            #pragma unroll
            for (int m = 0; m < 8; m++) {
                size_t row = (size_t)(m0+mb+m)*DQKV + off;
                g_qkv[row + cp]      = f0[m];
                g_qkv[row + cp + 64] = f1[m];
            }
        }
    } else {
        // head: 32 tokens x 8 outputs = 256 values (one per thread)
        int m = t >> 3, cc = t & 7;
        float acc = bh[cc];
        #pragma unroll 8
        for (int k = 0; k < DM; k++)
            acc = fmaf(A[m*DM + k], Wh[k*8 + cc], acc);
        out[(size_t)(m0+m)*8 + cc] = acc;
    }
}

// ===========================================================================
extern "C" void kernel_launch(void* const* d_in, const int* in_sizes, int n_in,
                              void* d_out, int out_size)
{
    const float* E      = (const float*)d_in[0];
    const float* rho    = (const float*)d_in[1];
    const float* W_in1  = (const float*)d_in[2];
    const float* b_in1  = (const float*)d_in[3];
    const float* W_in2  = (const float*)d_in[4];
    const float* b_in2  = (const float*)d_in[5];
    const float* Wqkv   = (const float*)d_in[6];
    const float* bqkv   = (const float*)d_in[7];
    const float* Wo     = (const float*)d_in[8];
    const float* bo     = (const float*)d_in[9];
    const float* ln1g   = (const float*)d_in[10];
    const float* ln1b   = (const float*)d_in[11];
    const float* Wff1   = (const float*)d_in[12];
    const float* bff1   = (const float*)d_in[13];
    const float* Wff2   = (const float*)d_in[14];
    const float* bff2   = (const float*)d_in[15];
    const float* ln2g   = (const float*)d_in[16];
    const float* ln2b   = (const float*)d_in[17];
    const float* W_head = (const float*)d_in[18];
    const float* b_head = (const float*)d_in[19];
    float* out = (float*)d_out;

    static int smem_set = 0;
    if (!smem_set) {
        cudaFuncSetAttribute(k_post, cudaFuncAttributeMaxDynamicSharedMemorySize, SMEM_POST);
        smem_set = 1;
    }

    k_pre<<<NBLK, 256>>>(E, rho, W_in1, b_in1, W_in2, b_in2, Wqkv, bqkv);

    dim3 agrid(TT/32, NH, BB);
    for (int l = 0; l < 3; l++) {
        k_attn<<<agrid, 256>>>();
        int last = (l == 2);
        k_post<<<NBLK2, 256, SMEM_POST>>>(Wo + (size_t)l*DM*DM, bo + l*DM,
                              ln1g + l*DM, ln1b + l*DM,
                              Wff1 + (size_t)l*DM*DFFN, bff1 + l*DFFN,
                              Wff2 + (size_t)l*DFFN*DM, bff2 + l*DM,
                              ln2g + l*DM, ln2b + l*DM,
                              Wqkv + (size_t)(l+1)*DM*DQKV, bqkv + (l+1)*DQKV,
                              W_head, b_head, out, last);
    }
}